// round 8
// baseline (speedup 1.0000x reference)
#include <cuda_runtime.h>
#include <math.h>

#define NS 64          // coarse samples
#define NF 128         // fine samples
#define NC 192         // combined
#define WPB 8          // warps per block
#define FULL 0xffffffffu

// #{k in [0,128) : u_k < x}, u_k = 0.05 + k * (0.9/127)
__device__ __forceinline__ int count_u(float x) {
    int c = __float2int_ru((x - 0.05f) * (127.0f / 0.9f));
    return min(max(c, 0), NF);
}

__device__ __forceinline__ unsigned long long pack2(float lo, float hi) {
    unsigned long long r;
    asm("mov.b64 %0, {%1, %2};" : "=l"(r) : "f"(lo), "f"(hi));
    return r;
}
__device__ __forceinline__ void unpack2(unsigned long long v, float& lo, float& hi) {
    asm("mov.b64 {%0, %1}, %2;" : "=f"(lo), "=f"(hi) : "l"(v));
}
__device__ __forceinline__ unsigned long long addp(unsigned long long a, unsigned long long b) {
    unsigned long long r;
    asm("add.rn.f32x2 %0, %1, %2;" : "=l"(r) : "l"(a), "l"(b));
    return r;
}

__global__ __launch_bounds__(WPB * 32)
void pdf_sampler_kernel(const float* __restrict__ near_, const float* __restrict__ far_,
                        const float* __restrict__ density, const float* __restrict__ rgb,
                        float* __restrict__ zs_out, float* __restrict__ rgb_out,
                        float* __restrict__ depth_out, float* __restrict__ acc_out,
                        int B)
{
    __shared__ __align__(16) float s_z[WPB][NC];
    __shared__ __align__(16) int   s_cnt[WPB][NF];

    const int warp = threadIdx.x >> 5;
    const int lane = threadIdx.x & 31;
    const int ray  = blockIdx.x * WPB + warp;
    if (ray >= B) return;

    const float nr = near_[ray];
    const float fr = far_[ray];
    const float delta = (fr - nr) * (1.0f / NS);

    // ---- density: 2 elems per lane, coalesced float2 ----
    const float2 dv = *reinterpret_cast<const float2*>(density + (size_t)ray * NS + 2 * lane);
    const float e0 = dv.x * delta;
    const float e1 = dv.y * delta;

    // ---- warp inclusive prefix sum of optical depth (pair per lane) ----
    const float ps = e0 + e1;
    float s = ps;
    #pragma unroll
    for (int off = 1; off < 32; off <<= 1) {
        float v = __shfl_up_sync(FULL, s, off);
        if (lane >= off) s += v;
    }
    const float excl = s - ps;           // cum optical depth before elem 2*lane

    // weights: w_i = T_i * (1 - exp(-x_i)); 3 exps, rest by identity
    const float T0 = __expf(-excl);
    const float w0 = T0 * (1.0f - __expf(-e0));
    const float Tm = T0 - w0;            // = exp(-cum at 2*lane)
    const float w1 = Tm * (1.0f - __expf(-e1));
    const float Te = Tm - w1;            // = exp(-cum at 2*lane+1)

    // analytic mids
    const float m0 = fmaf((float)(2 * lane) + 0.5f, delta, nr);
    const float m1 = m0 + delta;

    // ---- rgb loads (6 contiguous floats per lane, coalesced) ----
    const float* rrow = rgb + (size_t)ray * (NS * 3) + 6 * lane;
    const float2 ra = *reinterpret_cast<const float2*>(rrow + 0);
    const float2 rb = *reinterpret_cast<const float2*>(rrow + 2);
    const float2 rc = *reinterpret_cast<const float2*>(rrow + 4);

    // ---- reductions (packed f32x2 butterflies): (rs,gs) and (bs,dsum) ----
    unsigned long long q0 = pack2(w0 * ra.x + w1 * rb.y,   // rs
                                  w0 * ra.y + w1 * rc.x);  // gs
    unsigned long long q1 = pack2(w0 * rb.x + w1 * rc.y,   // bs
                                  w0 * m0   + w1 * m1);    // dsum
    #pragma unroll
    for (int off = 16; off >= 1; off >>= 1) {
        q0 = addp(q0, __shfl_xor_sync(FULL, q0, off));
        q1 = addp(q1, __shfl_xor_sync(FULL, q1, off));
    }

    // total weight: exp(-ctot) is lane 31's Te
    const float wsum = 1.0f - __shfl_sync(FULL, Te, 31);
    const float inv  = __fdividef(1.0f, wsum + 1e-6f);

    // normalized cdf at this lane's two positions (registers only)
    const float cd0 = (1.0f - Tm) * inv;   // cdf[2*lane]
    const float cd1 = (1.0f - Te) * inv;   // cdf[2*lane+1]
    float cprev = __shfl_up_sync(FULL, cd1, 1);   // cdf[2*lane-1]
    if (lane == 0) cprev = 0.0f;

    // interval ends: interval 2*lane ends at kM, interval 2*lane+1 ends at kE
    const int kM = count_u(cd0);
    const int kE = count_u(cd1);

    // per-interval reciprocal denominators (guarded as in reference)
    const float dA  = cd0 - cprev;
    const float rdA = (dA < 1e-5f) ? 1.0f : __fdividef(1.0f, dA);
    const float dB  = cd1 - cd0;
    const float rdB = (dB < 1e-5f) ? 1.0f : __fdividef(1.0f, dB);

    // ---- histogram of interval ends -> prefix sum -> p(k) for all k ----
    int* cw = s_cnt[warp];
    reinterpret_cast<int4*>(cw)[lane] = make_int4(0, 0, 0, 0);
    __syncwarp();
    if (kM < NF) atomicAdd(&cw[kM], 1);
    if (kE < NF) atomicAdd(&cw[kE], 1);
    __syncwarp();

    const int4 c = reinterpret_cast<const int4*>(cw)[lane];
    const int t0 = c.x;
    const int t1 = t0 + c.y;
    const int t2 = t1 + c.z;
    const int t3 = t2 + c.w;
    int v = t3;
    #pragma unroll
    for (int off = 1; off < 32; off <<= 1) {
        int u = __shfl_up_sync(FULL, v, off);
        if (lane >= off) v += u;
    }
    const int pex = v - t3;              // exclusive prefix at k = 4*lane
    int pk[4] = { pex + t0, pex + t1, pex + t2, pex + t3 };

    float* zw = s_z[warp];
    const float ustep = 0.9f / 127.0f;

    // ---- balanced fine-sample pass: 4 samples per lane, branch-free ----
    #pragma unroll
    for (int j = 0; j < 4; ++j) {
        const int k = 4 * lane + j;
        const int p = pk[j];                          // = searchsorted(cdf, u_k, right)
        const float u = fmaf((float)k, ustep, 0.05f);
        const int psel  = min(p, 63);
        const int owner = psel >> 1;
        const float cbA = __shfl_sync(FULL, cprev, owner);
        const float cbB = __shfl_sync(FULL, cd0,   owner);
        const float rA  = __shfl_sync(FULL, rdA,   owner);
        const float rB  = __shfl_sync(FULL, rdB,   owner);
        const float cb  = (psel & 1) ? cbB : cbA;     // cdf[p-1]
        const float rd  = (psel & 1) ? rB  : rA;
        const int pc    = min(max(p, 1), 64);
        const float mb  = fmaf((float)pc - 0.5f, delta, nr);   // mids[pc-1]
        const float dm  = ((unsigned)(p - 1) < 63u) ? delta : 0.0f; // 0 at p=0,64
        const float z   = fmaf((u - cb) * rd, dm, mb);
        zw[k + pc] = z;                               // slot = k + clamp(p,1,64)
    }

    // ---- mids: slot = i + (# fine strictly before mid i) ----
    const int i0 = 2 * lane;
    zw[(i0 == 0) ? 0 : (i0 + kM)] = m0;
    zw[i0 + 1 + kE] = m1;
    __syncwarp();

    // ---- coalesced vectorized write of the merged row ----
    float4* zv = reinterpret_cast<float4*>(zs_out + (size_t)ray * NC);
    const float4* sv = reinterpret_cast<const float4*>(zw);
    zv[lane] = sv[lane];                             // 128 floats
    if (lane < 16) zv[32 + lane] = sv[32 + lane];    // remaining 64

    // ---- scalar outputs, distributed (all lanes hold reduced values) ----
    if (lane < 5) {
        float rs, gs, bs, dsum;
        unpack2(q0, rs, gs);
        unpack2(q1, bs, dsum);
        if (lane < 3) {
            const float val = (lane == 0) ? rs : (lane == 1) ? gs : bs;
            rgb_out[(size_t)ray * 3 + lane] = val;
        } else if (lane == 3) {
            depth_out[ray] = __fdividef(dsum, wsum + 1e-8f);
        } else {
            acc_out[ray] = wsum;
        }
    }
}

extern "C" void kernel_launch(void* const* d_in, const int* in_sizes, int n_in,
                              void* d_out, int out_size)
{
    const float* near_   = (const float*)d_in[0];
    const float* far_    = (const float*)d_in[1];
    const float* density = (const float*)d_in[2];
    const float* rgb     = (const float*)d_in[3];
    const int B = in_sizes[0];

    float* out   = (float*)d_out;
    float* zs    = out;                       // B * 192
    float* rgbo  = zs + (size_t)B * NC;       // B * 3
    float* depth = rgbo + (size_t)B * 3;      // B
    float* acc   = depth + B;                 // B

    const int blocks = (B + WPB - 1) / WPB;
    pdf_sampler_kernel<<<blocks, WPB * 32>>>(near_, far_, density, rgb,
                                             zs, rgbo, depth, acc, B);
}

// round 9
// speedup vs baseline: 1.3842x; 1.3842x over previous
#include <cuda_runtime.h>
#include <math.h>

#define NS 64          // coarse samples
#define NF 128         // fine samples
#define NC 192         // combined
#define WPB 8          // warps per block
#define FULL 0xffffffffu

// #{k in [0,128) : u_k < x}, u_k = 0.05 + k * (0.9/127)
__device__ __forceinline__ int count_u(float x) {
    int c = __float2int_ru((x - 0.05f) * (127.0f / 0.9f));
    return min(max(c, 0), NF);
}

__device__ __forceinline__ unsigned long long pack2(float lo, float hi) {
    unsigned long long r;
    asm("mov.b64 %0, {%1, %2};" : "=l"(r) : "f"(lo), "f"(hi));
    return r;
}
__device__ __forceinline__ void unpack2(unsigned long long v, float& lo, float& hi) {
    asm("mov.b64 {%0, %1}, %2;" : "=f"(lo), "=f"(hi) : "l"(v));
}
__device__ __forceinline__ unsigned long long addp(unsigned long long a, unsigned long long b) {
    unsigned long long r;
    asm("add.rn.f32x2 %0, %1, %2;" : "=l"(r) : "l"(a), "l"(b));
    return r;
}

__global__ __launch_bounds__(WPB * 32)
void pdf_sampler_kernel(const float* __restrict__ near_, const float* __restrict__ far_,
                        const float* __restrict__ density, const float* __restrict__ rgb,
                        float* __restrict__ zs_out, float* __restrict__ rgb_out,
                        float* __restrict__ depth_out, float* __restrict__ acc_out,
                        int B)
{
    __shared__ __align__(16) float  s_z[WPB][NC];    // staging; first 512B alias S[]
    __shared__ __align__(8)  float2 s_par[WPB][NS + 2];  // (cb, g) per interval, + tail

    const int warp = threadIdx.x >> 5;
    const int lane = threadIdx.x & 31;
    const int ray  = blockIdx.x * WPB + warp;
    if (ray >= B) return;

    const float nr = near_[ray];
    const float fr = far_[ray];
    const float delta = (fr - nr) * (1.0f / NS);

    // ---- density: 2 elems per lane, coalesced float2 ----
    const float2 dv = *reinterpret_cast<const float2*>(density + (size_t)ray * NS + 2 * lane);
    const float e0 = dv.x * delta;
    const float e1 = dv.y * delta;

    // ---- warp inclusive prefix sum of optical depth (pair per lane) ----
    const float ps = e0 + e1;
    float s = ps;
    #pragma unroll
    for (int off = 1; off < 32; off <<= 1) {
        float v = __shfl_up_sync(FULL, s, off);
        if (lane >= off) s += v;
    }
    const float excl = s - ps;           // cum optical depth before elem 2*lane

    // weights: 3 exps, rest by identity
    const float T0 = __expf(-excl);
    const float w0 = T0 * (1.0f - __expf(-e0));
    const float Tm = T0 - w0;            // = exp(-cum at 2*lane)
    const float w1 = Tm * (1.0f - __expf(-e1));
    const float Te = Tm - w1;            // = exp(-cum at 2*lane+1)

    // analytic mids
    const float m0 = fmaf((float)(2 * lane) + 0.5f, delta, nr);
    const float m1 = m0 + delta;

    // ---- rgb loads (6 contiguous floats per lane, coalesced) ----
    const float* rrow = rgb + (size_t)ray * (NS * 3) + 6 * lane;
    const float2 ra = *reinterpret_cast<const float2*>(rrow + 0);
    const float2 rb = *reinterpret_cast<const float2*>(rrow + 2);
    const float2 rc = *reinterpret_cast<const float2*>(rrow + 4);

    // ---- reductions (packed f32x2 butterflies): (rs,gs) and (bs,dsum) ----
    unsigned long long q0 = pack2(w0 * ra.x + w1 * rb.y,   // rs
                                  w0 * ra.y + w1 * rc.x);  // gs
    unsigned long long q1 = pack2(w0 * rb.x + w1 * rc.y,   // bs
                                  w0 * m0   + w1 * m1);    // dsum
    #pragma unroll
    for (int off = 16; off >= 1; off >>= 1) {
        q0 = addp(q0, __shfl_xor_sync(FULL, q0, off));
        q1 = addp(q1, __shfl_xor_sync(FULL, q1, off));
    }

    // total weight: exp(-ctot) is lane 31's Te
    const float wsum = 1.0f - __shfl_sync(FULL, Te, 31);
    const float inv  = __fdividef(1.0f, wsum + 1e-6f);

    // normalized cdf at this lane's two positions
    const float cd0 = (1.0f - Tm) * inv;   // cdf[2*lane]
    const float cd1 = (1.0f - Te) * inv;   // cdf[2*lane+1]
    float cprev = __shfl_up_sync(FULL, cd1, 1);   // cdf[2*lane-1]
    if (lane == 0) cprev = 0.0f;

    // interval boundaries in fine-sample index space
    const int kS = count_u(cprev);   // start of interval i0
    const int kM = count_u(cd0);     // start of interval i1 (= end of i0)
    const int kE = count_u(cd1);     // end of interval i1

    const int i0 = 2 * lane;
    const int i1 = i0 + 1;

    // per-interval affine params: z = fmaf(u - cb, g, mids[pc-1])
    const float dA  = cd0 - cprev;
    const float rdA = (dA < 1e-5f) ? 1.0f : __fdividef(1.0f, dA);
    const float gA  = (i0 == 0) ? 0.0f : rdA * delta;   // p=0: z = mids[0]
    const float dB  = cd1 - cd0;
    const float rdB = (dB < 1e-5f) ? 1.0f : __fdividef(1.0f, dB);
    const float gB  = rdB * delta;

    float* zw = s_z[warp];
    int*   Sw = reinterpret_cast<int*>(zw);   // S[] aliases staging (consumed before z writes)
    float2* pw = s_par[warp];

    // ---- S init + params + interval-start marks (no atomics; starts distinct) ----
    reinterpret_cast<int4*>(Sw)[lane] = make_int4(0, 0, 0, 0);
    pw[i0] = make_float2(cprev, gA);
    pw[i1] = make_float2(cd0,  gB);
    if (lane == 31) pw[NS] = make_float2(0.0f, 0.0f);   // tail p=64: z = mids[63]
    __syncwarp();
    if (kS < kM) Sw[kS] = i0;
    if (kM < kE) Sw[kM] = i1;
    if (lane == 31 && kE < NF) Sw[kE] = NS;             // tail interval start
    __syncwarp();

    // ---- p(k) = inclusive max-scan of S ----
    const int4 c = reinterpret_cast<const int4*>(Sw)[lane];
    const int s0 = c.x;
    const int s1 = max(c.y, s0);
    const int s2 = max(c.z, s1);
    const int s3 = max(c.w, s2);
    int m = s3;
    #pragma unroll
    for (int off = 1; off < 32; off <<= 1) {
        int t = __shfl_up_sync(FULL, m, off);
        if (lane >= off) m = max(m, t);
    }
    int pex = __shfl_up_sync(FULL, m, 1);
    if (lane == 0) pex = 0;
    __syncwarp();   // S fully consumed; staging reuse begins

    // ---- balanced fine pass: 4 samples per lane, branch-free ----
    const float ustep = 0.9f / 127.0f;
    const float base  = nr - 0.5f * delta;       // mids[pc-1] = fmaf(pc, delta, base)
    const int pk0 = max(pex, s0), pk1 = max(pex, s1);
    const int pk2 = max(pex, s2), pk3 = max(pex, s3);
    #pragma unroll
    for (int j = 0; j < 4; ++j) {
        const int k = 4 * lane + j;
        const int p = (j == 0) ? pk0 : (j == 1) ? pk1 : (j == 2) ? pk2 : pk3;
        const int pc = min(max(p, 1), NS);       // clamp(p,1,64)
        const float2 pr = pw[p];
        const float u  = fmaf((float)k, ustep, 0.05f);
        const float mb = fmaf((float)pc, delta, base);
        zw[k + pc] = fmaf(u - pr.x, pr.y, mb);   // slot = k + clamp(p,1,64)
    }

    // ---- mids: slot = i + (# fine strictly before mid i) ----
    zw[(i0 == 0) ? 0 : (i0 + kM)] = m0;
    zw[i1 + kE] = m1;
    __syncwarp();

    // ---- coalesced vectorized write of the merged row ----
    float4* zv = reinterpret_cast<float4*>(zs_out + (size_t)ray * NC);
    const float4* sv = reinterpret_cast<const float4*>(zw);
    zv[lane] = sv[lane];                             // 128 floats
    if (lane < 16) zv[32 + lane] = sv[32 + lane];    // remaining 64

    // ---- scalar outputs, distributed ----
    if (lane < 5) {
        float rs, gs, bs, dsum;
        unpack2(q0, rs, gs);
        unpack2(q1, bs, dsum);
        if (lane < 3) {
            const float val = (lane == 0) ? rs : (lane == 1) ? gs : bs;
            rgb_out[(size_t)ray * 3 + lane] = val;
        } else if (lane == 3) {
            depth_out[ray] = __fdividef(dsum, wsum + 1e-8f);
        } else {
            acc_out[ray] = wsum;
        }
    }
}

extern "C" void kernel_launch(void* const* d_in, const int* in_sizes, int n_in,
                              void* d_out, int out_size)
{
    const float* near_   = (const float*)d_in[0];
    const float* far_    = (const float*)d_in[1];
    const float* density = (const float*)d_in[2];
    const float* rgb     = (const float*)d_in[3];
    const int B = in_sizes[0];

    float* out   = (float*)d_out;
    float* zs    = out;                       // B * 192
    float* rgbo  = zs + (size_t)B * NC;       // B * 3
    float* depth = rgbo + (size_t)B * 3;      // B
    float* acc   = depth + B;                 // B

    const int blocks = (B + WPB - 1) / WPB;
    pdf_sampler_kernel<<<blocks, WPB * 32>>>(near_, far_, density, rgb,
                                             zs, rgbo, depth, acc, B);
}

// round 10
// speedup vs baseline: 1.4868x; 1.0742x over previous
#include <cuda_runtime.h>
#include <math.h>

#define NS 64          // coarse samples
#define NF 128         // fine samples
#define NC 192         // combined
#define WPB 8          // warps per block
#define FULL 0xffffffffu

// #{k in [0,128) : u_k < x}, u_k = 0.05 + k * (0.9/127)
__device__ __forceinline__ int count_u(float x) {
    int c = __float2int_ru((x - 0.05f) * (127.0f / 0.9f));
    return min(max(c, 0), NF);
}

__device__ __forceinline__ unsigned long long pack2(float lo, float hi) {
    unsigned long long r;
    asm("mov.b64 %0, {%1, %2};" : "=l"(r) : "f"(lo), "f"(hi));
    return r;
}
__device__ __forceinline__ void unpack2(unsigned long long v, float& lo, float& hi) {
    asm("mov.b64 {%0, %1}, %2;" : "=f"(lo), "=f"(hi) : "l"(v));
}
__device__ __forceinline__ unsigned long long addp(unsigned long long a, unsigned long long b) {
    unsigned long long r;
    asm("add.rn.f32x2 %0, %1, %2;" : "=l"(r) : "l"(a), "l"(b));
    return r;
}

__global__ __launch_bounds__(WPB * 32, 8)
void pdf_sampler_kernel(const float* __restrict__ near_, const float* __restrict__ far_,
                        const float* __restrict__ density, const float* __restrict__ rgb,
                        float* __restrict__ zs_out, float* __restrict__ rgb_out,
                        float* __restrict__ depth_out, float* __restrict__ acc_out,
                        int B)
{
    __shared__ __align__(16) float  s_z[WPB][NC];    // staging; first 512B alias S[]
    __shared__ __align__(8)  float2 s_par[WPB][NS + 2];  // (cb, g) per interval, + tail

    const int warp = threadIdx.x >> 5;
    const int lane = threadIdx.x & 31;
    const int ray  = blockIdx.x * WPB + warp;
    if (ray >= B) return;

    const float nr = near_[ray];
    const float fr = far_[ray];
    const float delta = (fr - nr) * (1.0f / NS);

    // ---- density: 2 elems per lane, coalesced float2 ----
    const float2 dv = *reinterpret_cast<const float2*>(density + (size_t)ray * NS + 2 * lane);
    const float e0 = dv.x * delta;
    const float e1 = dv.y * delta;

    // ---- warp inclusive prefix sum of optical depth (pair per lane) ----
    const float ps = e0 + e1;
    float s = ps;
    #pragma unroll
    for (int off = 1; off < 32; off <<= 1) {
        float v = __shfl_up_sync(FULL, s, off);
        if (lane >= off) s += v;
    }
    const float excl = s - ps;           // cum optical depth before elem 2*lane

    // weights: 3 exps, rest by identity
    const float T0 = __expf(-excl);
    const float w0 = T0 * (1.0f - __expf(-e0));
    const float Tm = T0 - w0;            // = exp(-cum at 2*lane)
    const float w1 = Tm * (1.0f - __expf(-e1));
    const float Te = Tm - w1;            // = exp(-cum at 2*lane+1)

    // analytic mids
    const float m0 = fmaf((float)(2 * lane) + 0.5f, delta, nr);
    const float m1 = m0 + delta;

    // ---- rgb loads (6 contiguous floats per lane, coalesced) ----
    const float* rrow = rgb + (size_t)ray * (NS * 3) + 6 * lane;
    const float2 ra = *reinterpret_cast<const float2*>(rrow + 0);
    const float2 rb = *reinterpret_cast<const float2*>(rrow + 2);
    const float2 rc = *reinterpret_cast<const float2*>(rrow + 4);

    // ---- reductions (packed f32x2 butterflies): (rs,gs) and (bs,dsum) ----
    unsigned long long q0 = pack2(w0 * ra.x + w1 * rb.y,   // rs
                                  w0 * ra.y + w1 * rc.x);  // gs
    unsigned long long q1 = pack2(w0 * rb.x + w1 * rc.y,   // bs
                                  w0 * m0   + w1 * m1);    // dsum
    #pragma unroll
    for (int off = 16; off >= 1; off >>= 1) {
        q0 = addp(q0, __shfl_xor_sync(FULL, q0, off));
        q1 = addp(q1, __shfl_xor_sync(FULL, q1, off));
    }

    // total weight: exp(-ctot) is lane 31's Te
    const float wsum = 1.0f - __shfl_sync(FULL, Te, 31);
    const float inv  = __fdividef(1.0f, wsum + 1e-6f);

    // normalized cdf at this lane's two positions
    const float cd0 = (1.0f - Tm) * inv;   // cdf[2*lane]
    const float cd1 = (1.0f - Te) * inv;   // cdf[2*lane+1]
    float cprev = __shfl_up_sync(FULL, cd1, 1);   // cdf[2*lane-1]
    if (lane == 0) cprev = 0.0f;

    // interval boundaries in fine-sample index space
    const int kS = count_u(cprev);   // start of interval i0
    const int kM = count_u(cd0);     // start of interval i1 (= end of i0)
    const int kE = count_u(cd1);     // end of interval i1

    const int i0 = 2 * lane;
    const int i1 = i0 + 1;

    // per-interval affine params: z = fmaf(u - cb, g, mids[pc-1])
    const float dA  = cd0 - cprev;
    const float rdA = (dA < 1e-5f) ? 1.0f : __fdividef(1.0f, dA);
    const float gA  = (i0 == 0) ? 0.0f : rdA * delta;   // p=0: z = mids[0]
    const float dB  = cd1 - cd0;
    const float rdB = (dB < 1e-5f) ? 1.0f : __fdividef(1.0f, dB);
    const float gB  = rdB * delta;

    float* zw = s_z[warp];
    int*   Sw = reinterpret_cast<int*>(zw);   // S[] aliases staging (consumed before z writes)
    float2* pw = s_par[warp];

    // ---- S init + params + interval-start marks (no atomics; starts distinct) ----
    reinterpret_cast<int4*>(Sw)[lane] = make_int4(0, 0, 0, 0);
    pw[i0] = make_float2(cprev, gA);
    pw[i1] = make_float2(cd0,  gB);
    if (lane == 31) pw[NS] = make_float2(0.0f, 0.0f);   // tail p=64: z = mids[63]
    __syncwarp();
    if (kS < kM) Sw[kS] = i0;
    if (kM < kE) Sw[kM] = i1;
    if (lane == 31 && kE < NF) Sw[kE] = NS;             // tail interval start
    __syncwarp();

    // ---- p(k) = inclusive max-scan of S ----
    const int4 c = reinterpret_cast<const int4*>(Sw)[lane];
    const int s0 = c.x;
    const int s1 = max(c.y, s0);
    const int s2 = max(c.z, s1);
    const int s3 = max(c.w, s2);
    int m = s3;
    #pragma unroll
    for (int off = 1; off < 32; off <<= 1) {
        int t = __shfl_up_sync(FULL, m, off);
        if (lane >= off) m = max(m, t);
    }
    int pex = __shfl_up_sync(FULL, m, 1);
    if (lane == 0) pex = 0;
    __syncwarp();   // S fully consumed; staging reuse begins

    // ---- balanced fine pass: 4 samples per lane, branch-free ----
    const float ustep = 0.9f / 127.0f;
    const float base  = nr - 0.5f * delta;       // mids[pc-1] = fmaf(pc, delta, base)
    const int pk0 = max(pex, s0), pk1 = max(pex, s1);
    const int pk2 = max(pex, s2), pk3 = max(pex, s3);
    #pragma unroll
    for (int j = 0; j < 4; ++j) {
        const int k = 4 * lane + j;
        const int p = (j == 0) ? pk0 : (j == 1) ? pk1 : (j == 2) ? pk2 : pk3;
        const int pc = min(max(p, 1), NS);       // clamp(p,1,64)
        const float2 pr = pw[p];
        const float u  = fmaf((float)k, ustep, 0.05f);
        const float mb = fmaf((float)pc, delta, base);
        zw[k + pc] = fmaf(u - pr.x, pr.y, mb);   // slot = k + clamp(p,1,64)
    }

    // ---- mids: slot = i + (# fine strictly before mid i) ----
    zw[(i0 == 0) ? 0 : (i0 + kM)] = m0;
    zw[i1 + kE] = m1;
    __syncwarp();

    // ---- coalesced vectorized write of the merged row ----
    float4* zv = reinterpret_cast<float4*>(zs_out + (size_t)ray * NC);
    const float4* sv = reinterpret_cast<const float4*>(zw);
    zv[lane] = sv[lane];                             // 128 floats
    if (lane < 16) zv[32 + lane] = sv[32 + lane];    // remaining 64

    // ---- scalar outputs, distributed ----
    if (lane < 5) {
        float rs, gs, bs, dsum;
        unpack2(q0, rs, gs);
        unpack2(q1, bs, dsum);
        if (lane < 3) {
            const float val = (lane == 0) ? rs : (lane == 1) ? gs : bs;
            rgb_out[(size_t)ray * 3 + lane] = val;
        } else if (lane == 3) {
            depth_out[ray] = __fdividef(dsum, wsum + 1e-8f);
        } else {
            acc_out[ray] = wsum;
        }
    }
}

extern "C" void kernel_launch(void* const* d_in, const int* in_sizes, int n_in,
                              void* d_out, int out_size)
{
    const float* near_   = (const float*)d_in[0];
    const float* far_    = (const float*)d_in[1];
    const float* density = (const float*)d_in[2];
    const float* rgb     = (const float*)d_in[3];
    const int B = in_sizes[0];

    float* out   = (float*)d_out;
    float* zs    = out;                       // B * 192
    float* rgbo  = zs + (size_t)B * NC;       // B * 3
    float* depth = rgbo + (size_t)B * 3;      // B
    float* acc   = depth + B;                 // B

    const int blocks = (B + WPB - 1) / WPB;
    pdf_sampler_kernel<<<blocks, WPB * 32>>>(near_, far_, density, rgb,
                                             zs, rgbo, depth, acc, B);
}